// round 3
// baseline (speedup 1.0000x reference)
#include <cuda_runtime.h>
#include <math.h>

namespace {
constexpr int B  = 4;
constexpr int L  = 2048;
constexpr int DM = 1024;
constexpr int H  = 16;
constexpr int DH = 64;
constexpr int U  = 38;          // int(5 * ln(2048))
constexpr int BH = B * H;       // 64
constexpr float SCALE = 0.125f; // 1/sqrt(64)
constexpr double LOGL = 7.624618986159398; // ln(2048)

__device__ float g_kl[BH * L];
__device__ float g_sume[BH * L];
__device__ int   g_idx[BH * U];
} // namespace

// Accurate exp(x) for |x| <= ~20: 2^(x*log2e), range-reduced, degree-7 poly.
// ~1 ulp, deterministic, immune to fast-math substitution of expf.
__device__ __forceinline__ float exp_acc(float x) {
    float t = x * 1.4426950408889634f;
    float n = rintf(t);
    float f = t - n;
    float p = 1.5252733804059840e-05f;
    p = fmaf(p, f, 1.5403530393381609e-04f);
    p = fmaf(p, f, 1.3333558146428443e-03f);
    p = fmaf(p, f, 9.6181291076284772e-03f);
    p = fmaf(p, f, 5.5504108664821580e-02f);
    p = fmaf(p, f, 2.4022650695910071e-01f);
    p = fmaf(p, f, 6.9314718055994531e-01f);
    p = fmaf(p, f, 1.0f);
    int ni = (int)n;
    return p * __int_as_float((ni + 127) << 23);
}

// ---------------------------------------------------------------------------
// Pass 1: per-query streaming KL score.
// KL(p||uniform) = sum_k p_k * s_k  -  log(sum_k exp(s_k))  +  log(L)
// fp32 tile sums (64 keys) -> fp64 running sums; final KL in fp64.
// Block = 128 threads = 128 queries of one (b,h). K streamed via smem tiles.
// ---------------------------------------------------------------------------
__global__ void __launch_bounds__(128) kl_pass(const float* __restrict__ Q,
                                               const float* __restrict__ Km) {
    const int bh = blockIdx.x;
    const int b  = bh >> 4;
    const int h  = bh & 15;
    const int q  = blockIdx.y * 128 + threadIdx.x;

    const float4* qp =
        reinterpret_cast<const float4*>(Q + ((size_t)b * L + q) * DM + h * DH);
    float4 qv[16];
#pragma unroll
    for (int i = 0; i < 16; ++i) qv[i] = qp[i];

    __shared__ float4 sK[64][16];   // 64 keys x 64 dims
    const float* Kbase = Km + (size_t)b * L * DM + h * DH;

    double sum_e = 0.0, sum_se = 0.0;

    for (int k0 = 0; k0 < L; k0 += 64) {
        __syncthreads();
#pragma unroll
        for (int i = 0; i < 8; ++i) {
            int idx = threadIdx.x + i * 128;  // 0..1023
            int kk  = idx >> 4;
            int d4  = idx & 15;
            sK[kk][d4] =
                reinterpret_cast<const float4*>(Kbase + (size_t)(k0 + kk) * DM)[d4];
        }
        __syncthreads();

        float te = 0.f, tse = 0.f;   // fp32 tile accumulators (64 terms each)
#pragma unroll 2
        for (int kk = 0; kk < 64; ++kk) {
            // 4 independent accumulators to break the FFMA RAW chain (lat 4)
            float s0 = 0.f, s1 = 0.f, s2 = 0.f, s3 = 0.f;
#pragma unroll
            for (int i = 0; i < 4; ++i) {
                float4 a = sK[kk][i * 4 + 0];
                float4 bb = sK[kk][i * 4 + 1];
                float4 c = sK[kk][i * 4 + 2];
                float4 d = sK[kk][i * 4 + 3];
                s0 += qv[i*4+0].x*a.x  + qv[i*4+0].y*a.y  + qv[i*4+0].z*a.z  + qv[i*4+0].w*a.w;
                s1 += qv[i*4+1].x*bb.x + qv[i*4+1].y*bb.y + qv[i*4+1].z*bb.z + qv[i*4+1].w*bb.w;
                s2 += qv[i*4+2].x*c.x  + qv[i*4+2].y*c.y  + qv[i*4+2].z*c.z  + qv[i*4+2].w*c.w;
                s3 += qv[i*4+3].x*d.x  + qv[i*4+3].y*d.y  + qv[i*4+3].z*d.z  + qv[i*4+3].w*d.w;
            }
            float s = ((s0 + s1) + (s2 + s3)) * SCALE;
            float e = exp_acc(s);
            te  += e;
            tse = fmaf(s, e, tse);
        }
        sum_e  += (double)te;
        sum_se += (double)tse;
    }

    const int gi = bh * L + q;
    g_sume[gi] = (float)sum_e;
    g_kl[gi]   = (float)(sum_se / sum_e - log(sum_e) + LOGL);
}

// ---------------------------------------------------------------------------
// Pass 2: iterative top-U argmax per (b,h). Ties -> lowest index (JAX top_k).
// Emits indices in descending-value order (rank order matters for attn_weights).
// ---------------------------------------------------------------------------
__global__ void __launch_bounds__(256) topk_pass() {
    const int bh  = blockIdx.x;
    const int tid = threadIdx.x;

    __shared__ float sv[L];
    __shared__ float rv[256];
    __shared__ int   ri[256];

    for (int i = tid; i < L; i += 256) sv[i] = g_kl[bh * L + i];
    __syncthreads();

    for (int u = 0; u < U; ++u) {
        float best = -INFINITY;
        int   bi   = L;
        for (int i = tid; i < L; i += 256) {
            float v = sv[i];
            if (v > best) { best = v; bi = i; }   // strided ascending: first win = lowest idx
        }
        rv[tid] = best;
        ri[tid] = bi;
        __syncthreads();
        for (int s = 128; s > 0; s >>= 1) {
            if (tid < s) {
                float v2 = rv[tid + s];
                int   i2 = ri[tid + s];
                if (v2 > rv[tid] || (v2 == rv[tid] && i2 < ri[tid])) {
                    rv[tid] = v2; ri[tid] = i2;
                }
            }
            __syncthreads();
        }
        if (tid == 0) {
            g_idx[bh * U + u] = ri[0];
            sv[ri[0]] = -INFINITY;
        }
        __syncthreads();
    }
}

// ---------------------------------------------------------------------------
// Pass 3: sparse attention for the U selected queries of each (b,h).
// Reuses pass-1 softmax denominators (sum of exp over full K, unshifted).
// One block per (b,h); K/V streamed through one shared tile buffer.
// ---------------------------------------------------------------------------
constexpr int KT3 = 64;

__global__ void __launch_bounds__(256) sparse_attn(const float* __restrict__ Q,
                                                   const float* __restrict__ Km,
                                                   const float* __restrict__ Vm,
                                                   float* __restrict__ out,
                                                   float* __restrict__ aw,
                                                   int write_aw) {
    const int bh  = blockIdx.x;
    const int b   = bh >> 4;
    const int h   = bh & 15;
    const int tid = threadIdx.x;

    __shared__ float qs[U][DH];          // selected queries
    __shared__ float se[U];              // softmax denominators from pass 1
    __shared__ int   qidx[U];
    __shared__ float tile[KT3][DH + 1];  // K tile, then V tile (padded: stride-64 reads)
    __shared__ float w[U][KT3];          // attention weights for current tile

    if (tid < U) {
        int qi = g_idx[bh * U + tid];
        qidx[tid] = qi;
        se[tid]   = g_sume[bh * L + qi];
    }
    __syncthreads();
    for (int i = tid; i < U * DH; i += 256) {
        int u = i / DH, d = i % DH;
        qs[u][d] = Q[((size_t)b * L + qidx[u]) * DM + h * DH + d];
    }

    float acc[10];
#pragma unroll
    for (int j = 0; j < 10; ++j) acc[j] = 0.f;

    const float* Kb = Km + (size_t)b * L * DM + h * DH;
    const float* Vb = Vm + (size_t)b * L * DM + h * DH;

    for (int k0 = 0; k0 < L; k0 += KT3) {
        // --- load K tile ---
        __syncthreads();
        for (int i = tid; i < KT3 * 16; i += 256) {
            int kk = i >> 4, d4 = i & 15;
            float4 v = reinterpret_cast<const float4*>(Kb + (size_t)(k0 + kk) * DM)[d4];
            tile[kk][d4 * 4 + 0] = v.x; tile[kk][d4 * 4 + 1] = v.y;
            tile[kk][d4 * 4 + 2] = v.z; tile[kk][d4 * 4 + 3] = v.w;
        }
        __syncthreads();
        // --- scores / weights ---
        for (int i = tid; i < U * KT3; i += 256) {
            int u = i / KT3, kk = i % KT3;
            float s = 0.f;
#pragma unroll
            for (int d = 0; d < DH; ++d) s = fmaf(qs[u][d], tile[kk][d], s);
            s *= SCALE;
            float ww = exp_acc(s) / se[u];
            w[u][kk] = ww;
            if (write_aw) aw[((size_t)bh * U + u) * L + k0 + kk] = ww;
        }
        __syncthreads();
        // --- load V tile (reuse buffer) ---
        for (int i = tid; i < KT3 * 16; i += 256) {
            int kk = i >> 4, d4 = i & 15;
            float4 v = reinterpret_cast<const float4*>(Vb + (size_t)(k0 + kk) * DM)[d4];
            tile[kk][d4 * 4 + 0] = v.x; tile[kk][d4 * 4 + 1] = v.y;
            tile[kk][d4 * 4 + 2] = v.z; tile[kk][d4 * 4 + 3] = v.w;
        }
        __syncthreads();
        // --- accumulate O += w * V ---
#pragma unroll
        for (int j = 0; j < 10; ++j) {
            int item = tid + j * 256;
            if (item < U * DH) {
                int u = item / DH, d = item % DH;
                float a = acc[j];
#pragma unroll
                for (int kk = 0; kk < KT3; ++kk) a = fmaf(w[u][kk], tile[kk][d], a);
                acc[j] = a;
            }
        }
    }
    __syncthreads();

#pragma unroll
    for (int j = 0; j < 10; ++j) {
        int item = tid + j * 256;
        if (item < U * DH) {
            int u = item / DH, d = item % DH;
            out[((size_t)b * L + qidx[u]) * DM + h * DH + d] = acc[j];
        }
    }
}

// ---------------------------------------------------------------------------
extern "C" void kernel_launch(void* const* d_in, const int* in_sizes, int n_in,
                              void* d_out, int out_size) {
    const float* Q = (const float*)d_in[0];
    const float* K = (const float*)d_in[1];
    const float* V = (const float*)d_in[2];
    float* out = (float*)d_out;

    const size_t out_elems = (size_t)B * L * DM;          // 8,388,608
    const size_t aw_elems  = (size_t)BH * U * L;          // 4,980,736
    const int write_aw = ((size_t)out_size >= out_elems + aw_elems) ? 1 : 0;
    float* aw = out + out_elems;

    // Non-selected query rows are zero; d_out is poisoned, so clear first region.
    cudaMemsetAsync(d_out, 0, out_elems * sizeof(float), 0);

    kl_pass<<<dim3(BH, L / 128), 128>>>(Q, K);
    topk_pass<<<BH, 256>>>();
    sparse_attn<<<BH, 256>>>(Q, K, V, out, aw, write_aw);
}